// round 6
// baseline (speedup 1.0000x reference)
#include <cuda_runtime.h>

#define NB 2
#define NN 192
#define NF 5
#define NSPLIT 2
#define THREADS 256
#define NWARP 8
#define NGRP (NSPLIT*NWARP)   // 16 row-tile groups
#define NTILE (NN/2)          // 96 tiles of 2 rows

__device__ __forceinline__ float ex2f(float x) {
    float y;
    asm("ex2.approx.ftz.f32 %0, %1;" : "=f"(y) : "f"(x));
    return y;
}

__global__ __launch_bounds__(THREADS, 5)
void fa_kernel(const float* __restrict__ d, const float* __restrict__ cd,
               const float* __restrict__ fp, const float* __restrict__ coeff,
               float* __restrict__ out)
{
    const int blk  = blockIdx.x;
    const int b    = blk / (NN * NSPLIT);
    const int rem  = blk % (NN * NSPLIT);
    const int i    = rem >> 1;
    const int c    = rem & 1;
    const int tid  = threadIdx.x;
    const int lane = tid & 31;
    const int w    = tid >> 5;

    __shared__ float4 sP[NN];        // (d^2, 1/(sqrt2*d), sqrt2*cd0, 0); zeroed at ==i
    __shared__ float  sFp[NF], sC2[NF];
    __shared__ float  sRed[NWARP * NF];
    __shared__ float  sS[NWARP], sSS[NWARP];
    __shared__ float  sCdii;

    if (tid < NF) {
        sFp[tid] = fp[tid];
        sC2[tid] = -144.26950408889634f * coeff[tid];   // -100*log2(e)*coeff
    }

    const float* __restrict__ drow  = d  + ((size_t)b * NN + i) * NN;
    const float* __restrict__ cdrow = cd + ((size_t)b * NN + i) * NN;

    // ---- Phase 1: per-k precompute (+ S/SS partials, used by c==0 only) ----
    float pS = 0.f, pSS = 0.f;
    if (tid < NN) {
        float dv = drow[tid];
        float cv = cdrow[tid];
        float c0 = (cv == 1.0f) ? 0.0f : cv;
        pS  = c0;
        pSS = c0 * c0;
        bool isI = (tid == i);
        float rh = isI ? 0.0f : 0.70710678118654752f / dv;
        float wq = isI ? 0.0f : 1.41421356237309515f * c0;
        sP[tid] = make_float4(dv * dv, rh, wq, 0.0f);
        if (isI) sCdii = c0;
    }
    #pragma unroll
    for (int o = 16; o; o >>= 1) {
        pS  += __shfl_down_sync(0xFFFFFFFFu, pS,  o);
        pSS += __shfl_down_sync(0xFFFFFFFFu, pSS, o);
    }
    if (lane == 0) { sS[w] = pS; sSS[w] = pSS; }
    __syncthreads();

    float c2r[NF], mr[NF], qr[NF], acc[NF];
    #pragma unroll
    for (int f = 0; f < NF; f++) {
        float fpv = sFp[f], c2 = sC2[f];
        c2r[f] = c2;
        mr[f]  = -2.0f * c2 * fpv;
        qr[f]  = c2 * fpv * fpv;
        acc[f] = 0.0f;
    }

    // ---- Phase 2: 2-row register-blocked triangle sweep ----
    // Group g = c*8 + w owns tiles t ≡ g (mod 16); tile t = rows {2t, 2t+1}.
    // Exactly one masked iteration per tile (m == F); m < F iterations are full.
    const float* __restrict__ dmat = d + (size_t)b * NN * NN;
    const int g = c * NWARP + w;

    for (int t = g; t < NTILE; t += NGRP) {
        const int k0 = t << 1;
        const int k1 = k0 + 1;

        const float4 Pk0 = sP[k0];
        const float4 Pk1 = sP[k1];
        const float* __restrict__ r0 = dmat + (size_t)k0 * NN;

        const int F = k0 >> 5;          // full iterations; total T = F+1

        float dv0 = __ldg(r0 + lane);
        float dv1 = __ldg(r0 + NN + lane);
        float4 Pj = sP[lane];

        for (int m = 0; ; m++) {
            const float  e0 = dv0, e1 = dv1;
            const float4 Pc = Pj;
            const int    jc = lane + (m << 5);

            if (m < F) {                          // prefetch next chunk
                const int jn = jc + 32;
                dv0 = __ldg(r0 + jn);
                dv1 = __ldg(r0 + NN + jn);
                Pj  = sP[jn];
            }

            float num0 = fmaf(-e0, e0, Pk0.x + Pc.x);
            float num1 = fmaf(-e1, e1, Pk1.x + Pc.x);
            float ryc  = Pc.y;
            float a0   = (num0 * ryc) * Pk0.y;
            float a1   = (num1 * ryc) * Pk1.y;
            float a20  = a0 * a0;
            float a21  = a1 * a1;
            float w0   = Pk0.z * Pc.z;
            float w1   = Pk1.z * Pc.z;
            if (m >= F) {                          // warp-uniform tail mask
                w0 = (jc < k0) ? w0 : 0.0f;
                w1 = (jc < k1) ? w1 : 0.0f;
            }

            #pragma unroll
            for (int f = 0; f < NF; f++) {
                float arg0 = fmaf(c2r[f], a20, fmaf(mr[f], a0, qr[f]));
                float arg1 = fmaf(c2r[f], a21, fmaf(mr[f], a1, qr[f]));
                acc[f] = fmaf(ex2f(arg0), w0, acc[f]);
                acc[f] = fmaf(ex2f(arg1), w1, acc[f]);
            }

            if (m >= F) break;
        }
    }

    // ---- Reduce 5 accumulators within the CTA ----
    #pragma unroll
    for (int f = 0; f < NF; f++) {
        #pragma unroll
        for (int o = 16; o; o >>= 1)
            acc[f] += __shfl_down_sync(0xFFFFFFFFu, acc[f], o);
    }
    if (lane == 0) {
        #pragma unroll
        for (int f = 0; f < NF; f++) sRed[w * NF + f] = acc[f];
    }
    __syncthreads();

    // ---- Combine: exactly 2 atomic contributions per output cell.
    // Float add is commutative, so 2-way atomicAdd is bitwise deterministic.
    if (tid < NF) {
        float tacc = 0.f;
        #pragma unroll
        for (int wi = 0; wi < NWARP; wi++) tacc += sRed[wi * NF + tid];
        if (c == 0) {                    // analytic a=0 / a=1 terms once
            float S = 0.f, SS = 0.f;
            #pragma unroll
            for (int wi = 0; wi < NWARP; wi++) { S += sS[wi]; SS += sSS[wi]; }
            float cii = sCdii;
            float fpv = sFp[tid], c2v = sC2[tid];
            float g0 = ex2f((c2v * fpv) * fpv);        // a = 0 (j==i or k==i)
            float d1 = 1.0f - fpv;
            float g1 = ex2f((c2v * d1) * d1);          // a = 1 (diag j==k!=i)
            tacc += g0 * cii * (2.0f * S - cii) + g1 * (SS - cii * cii);
        }
        atomicAdd(&out[((size_t)b * NN + i) * NF + tid],
                  tacc * (1.0f / (NN * 12)));
    }
}

extern "C" void kernel_launch(void* const* d_in, const int* in_sizes, int n_in,
                              void* d_out, int out_size)
{
    const float* d     = (const float*)d_in[0];   // (B,N,N)
    const float* cd    = (const float*)d_in[1];   // (B,N,N)
    const float* fp    = (const float*)d_in[2];   // (5,)
    const float* coeff = (const float*)d_in[3];   // (5,)
    float* out = (float*)d_out;                   // (B,N,5)

    cudaMemsetAsync(d_out, 0, (size_t)out_size * sizeof(float));
    fa_kernel<<<NB * NN * NSPLIT, THREADS>>>(d, cd, fp, coeff, out);
}

// round 7
// speedup vs baseline: 1.0954x; 1.0954x over previous
#include <cuda_runtime.h>

#define NB 2
#define NN 192
#define NF 5
#define NSPLIT 2
#define THREADS 192
#define NWARP 6
#define NGRP (NSPLIT*NWARP)   // 12 tile groups
#define NTILE (NN/4)          // 48 tiles of 4 rows

__device__ __forceinline__ float ex2f(float x) {
    float y;
    asm("ex2.approx.ftz.f32 %0, %1;" : "=f"(y) : "f"(x));
    return y;
}

__global__ __launch_bounds__(THREADS, 5)
void fa_kernel(const float* __restrict__ d, const float* __restrict__ cd,
               const float* __restrict__ fp, const float* __restrict__ coeff,
               float* __restrict__ out)
{
    const int blk  = blockIdx.x;
    const int b    = blk / (NN * NSPLIT);
    const int rem  = blk % (NN * NSPLIT);
    const int i    = rem >> 1;
    const int c    = rem & 1;
    const int tid  = threadIdx.x;
    const int lane = tid & 31;
    const int w    = tid >> 5;

    __shared__ float4 sP[NN];        // (d^2, 1/(sqrt2*d), sqrt2*cd0, 0); zeroed at ==i
    __shared__ float  sFp[NF], sC2[NF];
    __shared__ float  sRed[NWARP * NF];
    __shared__ float  sS[NWARP], sSS[NWARP];
    __shared__ float  sCdii;

    if (tid < NF) {
        sFp[tid] = fp[tid];
        sC2[tid] = -144.26950408889634f * coeff[tid];   // -100*log2(e)*coeff
    }

    const float* __restrict__ drow  = d  + ((size_t)b * NN + i) * NN;
    const float* __restrict__ cdrow = cd + ((size_t)b * NN + i) * NN;

    // ---- Phase 1: per-k precompute + S/SS partials (192 threads = NN) ----
    {
        float dv = drow[tid];
        float cv = cdrow[tid];
        float c0 = (cv == 1.0f) ? 0.0f : cv;
        float pS = c0, pSS = c0 * c0;
        bool isI = (tid == i);
        float rh = isI ? 0.0f : 0.70710678118654752f / dv;
        float wq = isI ? 0.0f : 1.41421356237309515f * c0;
        sP[tid] = make_float4(dv * dv, rh, wq, 0.0f);
        if (isI) sCdii = c0;
        #pragma unroll
        for (int o = 16; o; o >>= 1) {
            pS  += __shfl_down_sync(0xFFFFFFFFu, pS,  o);
            pSS += __shfl_down_sync(0xFFFFFFFFu, pSS, o);
        }
        if (lane == 0) { sS[w] = pS; sSS[w] = pSS; }
    }
    __syncthreads();

    float c2r[NF], mr[NF], qr[NF], acc[NF];
    #pragma unroll
    for (int f = 0; f < NF; f++) {
        float fpv = sFp[f], c2 = sC2[f];
        c2r[f] = c2;
        mr[f]  = -2.0f * c2 * fpv;
        qr[f]  = c2 * fpv * fpv;
        acc[f] = 0.0f;
    }

    // ---- Phase 2: 4-row register-blocked triangle sweep ----
    // Group g = c*NWARP + w owns tiles t ≡ g (mod 12); tile t = rows 4t..4t+3.
    const float* __restrict__ dmat = d + (size_t)b * NN * NN;
    const int g = c * NWARP + w;

    for (int t = g; t < NTILE; t += NGRP) {
        const int k0 = t << 2;

        float4 Pk[4];
        const float* __restrict__ rp[4];
        #pragma unroll
        for (int q = 0; q < 4; q++) {
            Pk[q] = sP[k0 + q];
            rp[q] = dmat + (size_t)(k0 + q) * NN;
        }

        const int T = (k0 + 34) >> 5;   // covers j <= k0+2
        const int F = k0 >> 5;          // m < F: fully inside triangle

        float dv[4];
        #pragma unroll
        for (int q = 0; q < 4; q++) dv[q] = __ldg(rp[q] + lane);
        float4 Pj = sP[lane];

        for (int m = 0; m < T; m++) {
            float ev[4];
            #pragma unroll
            for (int q = 0; q < 4; q++) ev[q] = dv[q];
            float4 Pc = Pj;
            const int jc = lane + (m << 5);

            if (m + 1 < T) {
                const int jn = jc + 32;
                #pragma unroll
                for (int q = 0; q < 4; q++) dv[q] = __ldg(rp[q] + jn);
                Pj = sP[jn];
            }

            float av[4], a2v[4], wv[4];
            #pragma unroll
            for (int q = 0; q < 4; q++) {
                float num = fmaf(-ev[q], ev[q], Pk[q].x + Pc.x);
                float a   = (num * Pc.y) * Pk[q].y;
                av[q]  = a;
                a2v[q] = a * a;
                wv[q]  = Pk[q].z * Pc.z;
            }
            if (m >= F) {                         // warp-uniform tail mask
                #pragma unroll
                for (int q = 0; q < 4; q++)
                    wv[q] = (jc < k0 + q) ? wv[q] : 0.0f;
            }

            #pragma unroll
            for (int q = 0; q < 4; q++) {
                #pragma unroll
                for (int f = 0; f < NF; f++) {
                    float arg = fmaf(c2r[f], a2v[q], fmaf(mr[f], av[q], qr[f]));
                    acc[f] = fmaf(ex2f(arg), wv[q], acc[f]);
                }
            }
        }
    }

    // ---- Reduce 5 accumulators within the CTA ----
    #pragma unroll
    for (int f = 0; f < NF; f++) {
        #pragma unroll
        for (int o = 16; o; o >>= 1)
            acc[f] += __shfl_down_sync(0xFFFFFFFFu, acc[f], o);
    }
    if (lane == 0) {
        #pragma unroll
        for (int f = 0; f < NF; f++) sRed[w * NF + f] = acc[f];
    }
    __syncthreads();

    // ---- Combine: exactly 2 atomic contributions per cell (commutative → deterministic)
    if (tid < NF) {
        float tacc = 0.f;
        #pragma unroll
        for (int wi = 0; wi < NWARP; wi++) tacc += sRed[wi * NF + tid];
        if (c == 0) {
            float S = 0.f, SS = 0.f;
            #pragma unroll
            for (int wi = 0; wi < NWARP; wi++) { S += sS[wi]; SS += sSS[wi]; }
            float cii = sCdii;
            float fpv = sFp[tid], c2v = sC2[tid];
            float g0 = ex2f((c2v * fpv) * fpv);        // a = 0 (j==i or k==i)
            float d1 = 1.0f - fpv;
            float g1 = ex2f((c2v * d1) * d1);          // a = 1 (diag j==k!=i)
            tacc += g0 * cii * (2.0f * S - cii) + g1 * (SS - cii * cii);
        }
        atomicAdd(&out[((size_t)b * NN + i) * NF + tid],
                  tacc * (1.0f / (NN * 12)));
    }
}

extern "C" void kernel_launch(void* const* d_in, const int* in_sizes, int n_in,
                              void* d_out, int out_size)
{
    const float* d     = (const float*)d_in[0];   // (B,N,N)
    const float* cd    = (const float*)d_in[1];   // (B,N,N)
    const float* fp    = (const float*)d_in[2];   // (5,)
    const float* coeff = (const float*)d_in[3];   // (5,)
    float* out = (float*)d_out;                   // (B,N,5)

    cudaMemsetAsync(d_out, 0, (size_t)out_size * sizeof(float));
    fa_kernel<<<NB * NN * NSPLIT, THREADS>>>(d, cd, fp, coeff, out);
}

// round 9
// speedup vs baseline: 1.1000x; 1.0042x over previous
#include <cuda_runtime.h>

#define NB 2
#define NN 192
#define NF 5
#define NSPLIT 3
#define THREADS 128
#define NWARP 4
#define NGRP (NSPLIT*NWARP)   // 12 tile groups
#define NTILE (NN/4)          // 48 tiles of 4 rows

__device__ float g_part[NB * NN * NSPLIT * NF];
__device__ int   g_cnt[NB * NN];          // zero-init; self-resetting

__device__ __forceinline__ float ex2f(float x) {
    float y;
    asm("ex2.approx.ftz.f32 %0, %1;" : "=f"(y) : "f"(x));
    return y;
}

__global__ __launch_bounds__(THREADS, 8)
void fa_kernel(const float* __restrict__ d, const float* __restrict__ cd,
               const float* __restrict__ fp, const float* __restrict__ coeff,
               float* __restrict__ out)
{
    const int blk  = blockIdx.x;
    const int bi   = blk / NSPLIT;        // b*NN + i
    const int c    = blk - bi * NSPLIT;
    const int b    = bi / NN;
    const int i    = bi - b * NN;
    const int tid  = threadIdx.x;
    const int lane = tid & 31;
    const int w    = tid >> 5;

    __shared__ float4 sP[NN];        // (d^2, 1/(sqrt2*d), sqrt2*cd0, 0); zeroed at ==i
    __shared__ float  sFp[NF], sC2[NF];
    __shared__ float  sRed[NWARP * NF];
    __shared__ float  sS[NWARP], sSS[NWARP];
    __shared__ float  sCdii;
    __shared__ int    sTicket;

    if (tid < NF) {
        sFp[tid] = fp[tid];
        sC2[tid] = -144.26950408889634f * coeff[tid];   // -100*log2(e)*coeff
    }

    const float* __restrict__ drow  = d  + ((size_t)b * NN + i) * NN;
    const float* __restrict__ cdrow = cd + ((size_t)b * NN + i) * NN;

    // ---- Phase 1: per-k precompute + S/SS partials ----
    {
        float pS = 0.f, pSS = 0.f;
        #pragma unroll
        for (int k = tid; k < NN; k += THREADS) {
            float dv = drow[k];
            float cv = cdrow[k];
            float c0 = (cv == 1.0f) ? 0.0f : cv;
            pS  += c0;
            pSS += c0 * c0;
            bool isI = (k == i);
            float rh = isI ? 0.0f : 0.70710678118654752f / dv;
            float wq = isI ? 0.0f : 1.41421356237309515f * c0;
            sP[k] = make_float4(dv * dv, rh, wq, 0.0f);
            if (isI) sCdii = c0;
        }
        #pragma unroll
        for (int o = 16; o; o >>= 1) {
            pS  += __shfl_down_sync(0xFFFFFFFFu, pS,  o);
            pSS += __shfl_down_sync(0xFFFFFFFFu, pSS, o);
        }
        if (lane == 0) { sS[w] = pS; sSS[w] = pSS; }
    }
    __syncthreads();

    float c2r[NF], mr[NF], qr[NF], acc[NF];
    #pragma unroll
    for (int f = 0; f < NF; f++) {
        float fpv = sFp[f], c2 = sC2[f];
        c2r[f] = c2;
        mr[f]  = -2.0f * c2 * fpv;
        qr[f]  = c2 * fpv * fpv;
        acc[f] = 0.0f;
    }

    // ---- Phase 2: 4-row register-blocked triangle sweep ----
    // Group g = c*NWARP + w owns tiles t ≡ g (mod 12); tile t = rows 4t..4t+3.
    const float* __restrict__ dmat = d + (size_t)b * NN * NN;
    const int g = c * NWARP + w;

    for (int t = g; t < NTILE; t += NGRP) {
        const int k0 = t << 2;

        float4 Pk[4];
        #pragma unroll
        for (int q = 0; q < 4; q++) Pk[q] = sP[k0 + q];

        const int T = (k0 + 34) >> 5;   // covers j <= k0+2
        const int F = k0 >> 5;          // m < F: fully inside triangle

        const float*  pg = dmat + (size_t)k0 * NN + lane;   // advancing row base
        const float4* ps = sP + lane;                       // advancing table ptr

        float dv[4];
        dv[0] = __ldg(pg);
        dv[1] = __ldg(pg + NN);
        dv[2] = __ldg(pg + 2 * NN);
        dv[3] = __ldg(pg + 3 * NN);
        float4 Pj = *ps;

        for (int m = 0; m < T; m++) {
            float ev[4];
            #pragma unroll
            for (int q = 0; q < 4; q++) ev[q] = dv[q];
            float4 Pc = Pj;

            if (m + 1 < T) {                  // prefetch next chunk
                pg += 32; ps += 32;
                dv[0] = __ldg(pg);
                dv[1] = __ldg(pg + NN);
                dv[2] = __ldg(pg + 2 * NN);
                dv[3] = __ldg(pg + 3 * NN);
                Pj = *ps;
            }

            float av[4], a2v[4], wv[4];
            #pragma unroll
            for (int q = 0; q < 4; q++) {
                float num = fmaf(-ev[q], ev[q], Pk[q].x + Pc.x);
                float a   = (num * Pc.y) * Pk[q].y;
                av[q]  = a;
                a2v[q] = a * a;
                wv[q]  = Pk[q].z * Pc.z;
            }
            if (m >= F) {                     // warp-uniform: single masked iter
                const int jc = lane + (m << 5);
                #pragma unroll
                for (int q = 0; q < 4; q++)
                    wv[q] = (jc < k0 + q) ? wv[q] : 0.0f;
            }

            #pragma unroll
            for (int q = 0; q < 4; q++) {
                #pragma unroll
                for (int f = 0; f < NF; f++) {
                    float arg = fmaf(c2r[f], a2v[q], fmaf(mr[f], av[q], qr[f]));
                    acc[f] = fmaf(ex2f(arg), wv[q], acc[f]);
                }
            }
        }
    }

    // ---- Reduce 5 accumulators within the CTA ----
    #pragma unroll
    for (int f = 0; f < NF; f++) {
        #pragma unroll
        for (int o = 16; o; o >>= 1)
            acc[f] += __shfl_down_sync(0xFFFFFFFFu, acc[f], o);
    }
    if (lane == 0) {
        #pragma unroll
        for (int f = 0; f < NF; f++) sRed[w * NF + f] = acc[f];
    }
    __syncthreads();

    // ---- Publish partial, take ticket; last CTA combines in FIXED order ----
    if (tid < NF) {
        float tacc = 0.f;
        #pragma unroll
        for (int wi = 0; wi < NWARP; wi++) tacc += sRed[wi * NF + tid];
        g_part[(bi * NSPLIT + c) * NF + tid] = tacc;
    }
    __threadfence();
    __syncthreads();
    if (tid == 0) sTicket = atomicAdd(&g_cnt[bi], 1);
    __syncthreads();

    if (sTicket == NSPLIT - 1) {              // last arriver combines
        __threadfence();                      // see peers' g_part stores
        if (tid < NF) {
            float tacc = 0.f;
            #pragma unroll
            for (int s = 0; s < NSPLIT; s++)  // fixed order -> deterministic
                tacc += g_part[(bi * NSPLIT + s) * NF + tid];
            float S = 0.f, SS = 0.f;
            #pragma unroll
            for (int wi = 0; wi < NWARP; wi++) { S += sS[wi]; SS += sSS[wi]; }
            float cii = sCdii;
            float fpv = sFp[tid], c2v = sC2[tid];
            float g0 = ex2f((c2v * fpv) * fpv);        // a = 0 (j==i or k==i)
            float d1 = 1.0f - fpv;
            float g1 = ex2f((c2v * d1) * d1);          // a = 1 (diag j==k!=i)
            tacc += g0 * cii * (2.0f * S - cii) + g1 * (SS - cii * cii);
            out[(size_t)bi * NF + tid] = tacc * (1.0f / (NN * 12));
        }
        if (tid == 0) atomicExch(&g_cnt[bi], 0);   // reset for next launch/replay
    }
}

extern "C" void kernel_launch(void* const* d_in, const int* in_sizes, int n_in,
                              void* d_out, int out_size)
{
    const float* d     = (const float*)d_in[0];   // (B,N,N)
    const float* cd    = (const float*)d_in[1];   // (B,N,N)
    const float* fp    = (const float*)d_in[2];   // (5,)
    const float* coeff = (const float*)d_in[3];   // (5,)
    float* out = (float*)d_out;                   // (B,N,5)

    fa_kernel<<<NB * NN * NSPLIT, THREADS>>>(d, cd, fp, coeff, out);
}

// round 11
// speedup vs baseline: 1.1094x; 1.0085x over previous
#include <cuda_runtime.h>

#define NB 2
#define NN 192
#define NF 5
#define THREADS 256
#define NWARP 8
#define NUNIT 96          // row-pair units (kA, 191-kA), each exactly 191 pairs

__device__ __forceinline__ float ex2f(float x) {
    float y;
    asm("ex2.approx.ftz.f32 %0, %1;" : "=f"(y) : "f"(x));
    return y;
}

__global__ __launch_bounds__(THREADS)
void fa_kernel(const float* __restrict__ d, const float* __restrict__ cd,
               const float* __restrict__ fp, const float* __restrict__ coeff,
               float* __restrict__ out)
{
    const int b    = blockIdx.x / NN;
    const int i    = blockIdx.x % NN;
    const int tid  = threadIdx.x;
    const int lane = tid & 31;
    const int w    = tid >> 5;

    __shared__ float4 sP[NN];        // (d^2, 1/(sqrt2*d), sqrt2*cd0, 0); zeroed at ==i
    __shared__ float  sFp[NF], sC2[NF];
    __shared__ float  sRed[NWARP * NF];
    __shared__ float  sS[NWARP], sSS[NWARP];
    __shared__ float  sCdii;

    if (tid < NF) {
        sFp[tid] = fp[tid];
        sC2[tid] = -144.26950408889634f * coeff[tid];   // -100*log2(e)*coeff
    }

    const float* __restrict__ drow  = d  + ((size_t)b * NN + i) * NN;
    const float* __restrict__ cdrow = cd + ((size_t)b * NN + i) * NN;

    // ---- Phase 1: per-k precompute + S/SS partials ----
    float pS = 0.f, pSS = 0.f;
    if (tid < NN) {
        float dv = drow[tid];
        float cv = cdrow[tid];
        float c0 = (cv == 1.0f) ? 0.0f : cv;
        pS  = c0;
        pSS = c0 * c0;
        bool isI = (tid == i);
        float rh = isI ? 0.0f : 0.70710678118654752f / dv;
        float wq = isI ? 0.0f : 1.41421356237309515f * c0;
        sP[tid] = make_float4(dv * dv, rh, wq, 0.0f);
        if (isI) sCdii = c0;
    }
    #pragma unroll
    for (int o = 16; o; o >>= 1) {
        pS  += __shfl_down_sync(0xFFFFFFFFu, pS,  o);
        pSS += __shfl_down_sync(0xFFFFFFFFu, pSS, o);
    }
    if (lane == 0) { sS[w] = pS; sSS[w] = pSS; }
    __syncthreads();

    float c2r[NF], mr[NF], qr[NF], acc[NF];
    #pragma unroll
    for (int f = 0; f < NF; f++) {
        float fpv = sFp[f], c2 = sC2[f];
        c2r[f] = c2;
        mr[f]  = -2.0f * c2 * fpv;
        qr[f]  = c2 * fpv * fpv;
        acc[f] = 0.0f;
    }

    // ---- Phase 2: trapezoid-folded triangle sweep ----
    // Unit r pairs rows kA=96+r (kA pairs: j<kA) and kB=95-r (kB pairs: j<kB);
    // kA+kB = 191 pairs -> exactly 6 warp-iterations of 32 slots (1 slot wasted).
    // Slot u in [0,192): u < kA -> (row kA, j=u), else (row kB, j=u-kA).
    // Rows/cols == i contribute 0 via masked sP entries.
    const float* __restrict__ dmat = d + (size_t)b * NN * NN;

    for (int r = w; r < NUNIT; r += NWARP) {
        const int kA = 96 + r;           // 96..191
        const int kB = 95 - r;           // 95..0

        const float4 PA = sP[kA];
        const float4 PB = sP[kB];
        const float* __restrict__ rowA = dmat + (size_t)kA * NN;
        const float* __restrict__ rowB = dmat + (size_t)kB * NN;

        #pragma unroll
        for (int m = 0; m < 6; m++) {
            const int  u  = lane + (m << 5);
            const bool pA = (u < kA);
            const int  j  = pA ? u : (u - kA);

            const float* __restrict__ rw = pA ? rowA : rowB;
            float  dv = __ldg(rw + j);
            float4 Pc = sP[j];

            float D2k = pA ? PA.x : PB.x;
            float rk  = pA ? PA.y : PB.y;
            float wk  = pA ? PA.z : PB.z;

            float num = fmaf(-dv, dv, D2k + Pc.x);   // d2j + d2k - djk^2
            float a   = (num * Pc.y) * rk;           // num / (2 d_ij d_ik)
            float a2  = a * a;
            float wgt = wk * Pc.z;                   // 2 cd0_j cd0_k
            if (m == 5) wgt = (u < 191) ? wgt : 0.0f;   // single wasted slot

            #pragma unroll
            for (int f = 0; f < NF; f++) {
                float arg = fmaf(c2r[f], a2, fmaf(mr[f], a, qr[f]));
                acc[f] = fmaf(ex2f(arg), wgt, acc[f]);
            }
        }
    }

    // ---- Reduce 5 accumulators ----
    #pragma unroll
    for (int f = 0; f < NF; f++) {
        #pragma unroll
        for (int o = 16; o; o >>= 1)
            acc[f] += __shfl_down_sync(0xFFFFFFFFu, acc[f], o);
    }
    if (lane == 0) {
        #pragma unroll
        for (int f = 0; f < NF; f++) sRed[w * NF + f] = acc[f];
    }
    __syncthreads();

    if (tid < NF) {
        float tacc = 0.f;
        #pragma unroll
        for (int wi = 0; wi < NWARP; wi++) tacc += sRed[wi * NF + tid];
        float S = 0.f, SS = 0.f;
        #pragma unroll
        for (int wi = 0; wi < NWARP; wi++) { S += sS[wi]; SS += sSS[wi]; }
        float cii = sCdii;
        float fpv = sFp[tid], c2v = sC2[tid];
        float g0 = ex2f((c2v * fpv) * fpv);        // a = 0 terms (j==i or k==i)
        float d1 = 1.0f - fpv;
        float g1 = ex2f((c2v * d1) * d1);          // a = 1 terms (diag j==k!=i)
        tacc += g0 * cii * (2.0f * S - cii) + g1 * (SS - cii * cii);
        out[blockIdx.x * NF + tid] = tacc * (1.0f / (NN * 12));
    }
}

extern "C" void kernel_launch(void* const* d_in, const int* in_sizes, int n_in,
                              void* d_out, int out_size)
{
    const float* d     = (const float*)d_in[0];   // (B,N,N)
    const float* cd    = (const float*)d_in[1];   // (B,N,N)
    const float* fp    = (const float*)d_in[2];   // (5,)
    const float* coeff = (const float*)d_in[3];   // (5,)
    float* out = (float*)d_out;                   // (B,N,5)

    fa_kernel<<<NB * NN, THREADS>>>(d, cd, fp, coeff, out);
}

// round 12
// speedup vs baseline: 1.1798x; 1.0634x over previous
#include <cuda_runtime.h>

#define NB 2
#define NN 192
#define NF 5
#define NSPLIT 2
#define THREADS 192
#define NWARP 6
#define NGRP (NSPLIT*NWARP)   // 12 unit groups
#define NUNIT 96              // row-pair units (kA=96+r, kB=95-r): 191 pairs each

__device__ float g_part[NB * NN * NSPLIT * NF];
__device__ int   g_cnt[NB * NN];          // zero-init; self-resetting

__device__ __forceinline__ float ex2f(float x) {
    float y;
    asm("ex2.approx.ftz.f32 %0, %1;" : "=f"(y) : "f"(x));
    return y;
}

__global__ __launch_bounds__(THREADS, 5)
void fa_kernel(const float* __restrict__ d, const float* __restrict__ cd,
               const float* __restrict__ fp, const float* __restrict__ coeff,
               float* __restrict__ out)
{
    const int blk  = blockIdx.x;
    const int bi   = blk >> 1;            // b*NN + i
    const int c    = blk & 1;
    const int b    = bi / NN;
    const int i    = bi - b * NN;
    const int tid  = threadIdx.x;
    const int lane = tid & 31;
    const int w    = tid >> 5;

    __shared__ float4 sP[NN];        // (d^2, 1/(sqrt2*d), sqrt2*cd0, 0); zeroed at ==i
    __shared__ float  sFp[NF], sC2[NF];
    __shared__ float  sRed[NWARP * NF];
    __shared__ float  sS[NWARP], sSS[NWARP];
    __shared__ float  sCdii;
    __shared__ int    sTicket;

    if (tid < NF) {
        sFp[tid] = fp[tid];
        sC2[tid] = -144.26950408889634f * coeff[tid];   // -100*log2(e)*coeff
    }

    const float* __restrict__ drow  = d  + ((size_t)b * NN + i) * NN;
    const float* __restrict__ cdrow = cd + ((size_t)b * NN + i) * NN;

    // ---- Phase 1: per-k precompute + S/SS partials (192 threads == NN) ----
    {
        float dv = drow[tid];
        float cv = cdrow[tid];
        float c0 = (cv == 1.0f) ? 0.0f : cv;
        float pS = c0, pSS = c0 * c0;
        bool isI = (tid == i);
        float rh = isI ? 0.0f : 0.70710678118654752f / dv;
        float wq = isI ? 0.0f : 1.41421356237309515f * c0;
        sP[tid] = make_float4(dv * dv, rh, wq, 0.0f);
        if (isI) sCdii = c0;
        #pragma unroll
        for (int o = 16; o; o >>= 1) {
            pS  += __shfl_down_sync(0xFFFFFFFFu, pS,  o);
            pSS += __shfl_down_sync(0xFFFFFFFFu, pSS, o);
        }
        if (lane == 0) { sS[w] = pS; sSS[w] = pSS; }
    }
    __syncthreads();

    float c2r[NF], mr[NF], qr[NF], acc[NF];
    #pragma unroll
    for (int f = 0; f < NF; f++) {
        float fpv = sFp[f], c2 = sC2[f];
        c2r[f] = c2;
        mr[f]  = -2.0f * c2 * fpv;
        qr[f]  = c2 * fpv * fpv;
        acc[f] = 0.0f;
    }

    // ---- Phase 2: trapezoid-folded triangle sweep ----
    // Unit r: rows kA=96+r (j<kA) and kB=95-r (j<kB); kA+kB=191 pairs ->
    // exactly 6 warp-iterations of 32 slots (slot u=191 wasted, masked).
    // Slot u: u<kA -> (row kA, j=u) else (row kB, j=u-kA).
    const float* __restrict__ dmat = d + (size_t)b * NN * NN;
    const int g = c * NWARP + w;          // 0..11; exactly 8 units per warp

    for (int r = g; r < NUNIT; r += NGRP) {
        const int kA = 96 + r;
        const float4 PA = sP[kA];
        const float4 PB = sP[95 - r];
        const float* __restrict__ rowA = dmat + (size_t)kA * NN;
        const float* __restrict__ rowB = dmat + (size_t)(95 - r) * NN - kA;  // index by u directly

        #pragma unroll
        for (int h = 0; h < 2; h++) {               // two half-batches of 3 slots
            float  dv[3];
            float4 Pc[3];
            int    jj[3];
            bool   pa[3];
            #pragma unroll
            for (int s = 0; s < 3; s++) {
                const int u = lane + ((h * 3 + s) << 5);
                const bool pA = (u < kA);
                const int  j  = pA ? u : (u - kA);
                pa[s] = pA;
                jj[s] = u;
                dv[s] = __ldg((pA ? rowA : rowB) + (pA ? u : u));  // rowB pre-offset by -kA
                Pc[s] = sP[j];
            }
            #pragma unroll
            for (int s = 0; s < 3; s++) {
                const bool pA = pa[s];
                const float D2k = pA ? PA.x : PB.x;
                const float rk  = pA ? PA.y : PB.y;
                const float wk  = pA ? PA.z : PB.z;

                float num = fmaf(-dv[s], dv[s], D2k + Pc[s].x);  // d2j+d2k-djk^2
                float a   = (num * Pc[s].y) * rk;                // /(2 d_ij d_ik)
                float a2  = a * a;
                float wgt = wk * Pc[s].z;                        // 2 cd0_j cd0_k
                if (h == 1 && s == 2) wgt = (jj[s] < 191) ? wgt : 0.0f;

                #pragma unroll
                for (int f = 0; f < NF; f++) {
                    float arg = fmaf(c2r[f], a2, fmaf(mr[f], a, qr[f]));
                    acc[f] = fmaf(ex2f(arg), wgt, acc[f]);
                }
            }
        }
    }

    // ---- Reduce 5 accumulators within the CTA ----
    #pragma unroll
    for (int f = 0; f < NF; f++) {
        #pragma unroll
        for (int o = 16; o; o >>= 1)
            acc[f] += __shfl_down_sync(0xFFFFFFFFu, acc[f], o);
    }
    if (lane == 0) {
        #pragma unroll
        for (int f = 0; f < NF; f++) sRed[w * NF + f] = acc[f];
    }
    __syncthreads();

    // ---- Publish partial, take ticket; last CTA combines in FIXED order ----
    if (tid < NF) {
        float tacc = 0.f;
        #pragma unroll
        for (int wi = 0; wi < NWARP; wi++) tacc += sRed[wi * NF + tid];
        g_part[(bi * NSPLIT + c) * NF + tid] = tacc;
    }
    __threadfence();
    __syncthreads();
    if (tid == 0) sTicket = atomicAdd(&g_cnt[bi], 1);
    __syncthreads();

    if (sTicket == NSPLIT - 1) {              // last arriver combines
        __threadfence();
        if (tid < NF) {
            float tacc = 0.f;
            #pragma unroll
            for (int s = 0; s < NSPLIT; s++)  // fixed order -> deterministic
                tacc += g_part[(bi * NSPLIT + s) * NF + tid];
            float S = 0.f, SS = 0.f;
            #pragma unroll
            for (int wi = 0; wi < NWARP; wi++) { S += sS[wi]; SS += sSS[wi]; }
            float cii = sCdii;
            float fpv = sFp[tid], c2v = sC2[tid];
            float g0 = ex2f((c2v * fpv) * fpv);        // a = 0 (j==i or k==i)
            float d1 = 1.0f - fpv;
            float g1 = ex2f((c2v * d1) * d1);          // a = 1 (diag j==k!=i)
            tacc += g0 * cii * (2.0f * S - cii) + g1 * (SS - cii * cii);
            out[(size_t)bi * NF + tid] = tacc * (1.0f / (NN * 12));
        }
        if (tid == 0) atomicExch(&g_cnt[bi], 0);   // reset for replay
    }
}

extern "C" void kernel_launch(void* const* d_in, const int* in_sizes, int n_in,
                              void* d_out, int out_size)
{
    const float* d     = (const float*)d_in[0];   // (B,N,N)
    const float* cd    = (const float*)d_in[1];   // (B,N,N)
    const float* fp    = (const float*)d_in[2];   // (5,)
    const float* coeff = (const float*)d_in[3];   // (5,)
    float* out = (float*)d_out;                   // (B,N,5)

    fa_kernel<<<NB * NN * NSPLIT, THREADS>>>(d, cd, fp, coeff, out);
}